// round 11
// baseline (speedup 1.0000x reference)
#include <cuda_runtime.h>
#include <math.h>
#include <stdint.h>

#define D_MODEL 768
#define D_HID   3072
#define NE      8
#define NTOK    2048
#define NPAIR   (NTOK * 2)
#define MAXPER  2048

// ---------------- device scratch ----------------------------------------------
// g_x / g_h hold tf32-rounded values in FRAGMENT-PERMUTED order: within each
// 8-word k-group, word j holds true k = ((j>>1)&3) + 4*(j&1)  (i.e. stored
// order [k0,k4,k1,k5,k2,k6,k3,k7]) so an MMA thread's (ks+c, ks+4+c) pair is
// one contiguous 8B LDS.64.
__device__ float g_h[(size_t)NPAIR * D_HID];
__device__ float g_x[(size_t)NTOK * D_MODEL];
__device__ float g_wgt[NPAIR];
__device__ int   g_list[NE * MAXPER];
__device__ int   g_cnt[NE];

// ---------------- helpers ------------------------------------------------------
__device__ __forceinline__ uint32_t smem_u32(const void* p) {
    uint32_t a;
    asm("{ .reg .u64 t; cvta.to.shared.u64 t, %1; cvt.u32.u64 %0, t; }" : "=r"(a) : "l"(p));
    return a;
}
__device__ __forceinline__ uint32_t f2tf32(float v) {
    uint32_t r;
    asm("cvt.rna.tf32.f32 %0, %1;" : "=r"(r) : "f"(v));
    return r;
}
__device__ __forceinline__ uint32_t bits2tf32(uint32_t b) {
    return f2tf32(__uint_as_float(b));
}
__device__ __forceinline__ void mma_tf32(float* c, uint32_t a0, uint32_t a1,
                                         uint32_t a2, uint32_t a3,
                                         uint32_t b0, uint32_t b1) {
    asm volatile(
        "mma.sync.aligned.m16n8k8.row.col.f32.tf32.tf32.f32 "
        "{%0,%1,%2,%3}, {%4,%5,%6,%7}, {%8,%9}, {%0,%1,%2,%3};"
        : "+f"(c[0]), "+f"(c[1]), "+f"(c[2]), "+f"(c[3])
        : "r"(a0), "r"(a1), "r"(a2), "r"(a3), "r"(b0), "r"(b1));
}
__device__ __forceinline__ void cpa16(uint32_t saddr, const void* g, uint32_t nbytes) {
    asm volatile("cp.async.cg.shared.global [%0], [%1], 16, %2;"
                 :: "r"(saddr), "l"(g), "r"(nbytes) : "memory");
}
__device__ __forceinline__ void cpa_commit() {
    asm volatile("cp.async.commit_group;" ::: "memory");
}
__device__ __forceinline__ void cpa_wait1() {
    asm volatile("cp.async.wait_group 1;" ::: "memory");
}
__device__ __forceinline__ float gelu_f(float v) {
    return 0.5f * v * (1.0f + erff(v * 0.70710678118654752f));
}
// permutation: true col/k c -> stored word index within its 8-group
__device__ __forceinline__ int permj(int c) {
    return (c & ~7) + 2 * (c & 3) + ((c >> 2) & 1);
}

// smem layout (words): [0..128) s_pair, then 3 stages of (A 128x40 | B 32x136)
#define LDA 40
#define LDB 136
#define A_ST_W (128 * LDA)              // 5120
#define B_ST_W (32 * LDB)               // 4352
#define STAGE_W (A_ST_W + B_ST_W)       // 9472 words = 37888 B
#define SP_W 128
#define SMEM_BYTES ((SP_W + 3 * STAGE_W) * 4)   // 114176 (2 CTAs/SM)

// ---------------- init: zero out + counters + permuted tf32 x -------------------
__global__ __launch_bounds__(256)
void init_kernel(float* __restrict__ out, const float* __restrict__ x) {
    int i = blockIdx.x * blockDim.x + threadIdx.x;
    if (i < NE) g_cnt[i] = 0;
    ((float4*)out)[i] = make_float4(0.f, 0.f, 0.f, 0.f);
    // write g_x float4 at words 4i..4i+3 in permuted order
    int j0 = 4 * i;
    float4 r;
    float* rp = (float*)&r;
#pragma unroll
    for (int q = 0; q < 4; q++) {
        int j = j0 + q;
        int k = (j & ~7) + ((j >> 1) & 3) + 4 * (j & 1);
        rp[q] = __uint_as_float(f2tf32(x[k]));
    }
    ((float4*)g_x)[i] = r;
}

// ---------------- router: one warp per token ----------------------------------
__global__ __launch_bounds__(256)
void router_kernel(const float* __restrict__ x, const float* __restrict__ gw) {
    int gwarp = (blockIdx.x * blockDim.x + threadIdx.x) >> 5;
    int lane  = threadIdx.x & 31;
    if (gwarp >= NTOK) return;
    const float* xr = x + (size_t)gwarp * D_MODEL;

    float acc[NE];
#pragma unroll
    for (int e = 0; e < NE; e++) acc[e] = 0.f;
    for (int d = lane; d < D_MODEL; d += 32) {
        float xv = xr[d];
#pragma unroll
        for (int e = 0; e < NE; e++) acc[e] += xv * gw[d * NE + e];
    }
#pragma unroll
    for (int e = 0; e < NE; e++) {
#pragma unroll
        for (int off = 16; off > 0; off >>= 1)
            acc[e] += __shfl_xor_sync(0xffffffffu, acc[e], off);
    }
    if (lane == 0) {
        float mx = acc[0];
#pragma unroll
        for (int e = 1; e < NE; e++) mx = fmaxf(mx, acc[e]);
        float p[NE];
#pragma unroll
        for (int e = 0; e < NE; e++) p[e] = __expf(acc[e] - mx);
        int i0 = 0;
#pragma unroll
        for (int e = 1; e < NE; e++) if (p[e] > p[i0]) i0 = e;
        int i1 = (i0 == 0) ? 1 : 0;
#pragma unroll
        for (int e = 0; e < NE; e++) if (e != i0 && p[e] > p[i1]) i1 = e;
        float s2 = p[i0] + p[i1];
        int pr0 = gwarp * 2, pr1 = gwarp * 2 + 1;
        g_wgt[pr0] = p[i0] / s2;
        g_wgt[pr1] = p[i1] / s2;
        int pos0 = atomicAdd(&g_cnt[i0], 1);
        g_list[i0 * MAXPER + pos0] = pr0;
        int pos1 = atomicAdd(&g_cnt[i1], 1);
        g_list[i1 * MAXPER + pos1] = pr1;
    }
}

// ======================= pipelined tf32 MMA GEMM bodies ========================
struct PipeCtx {
    const float* arow;
    uint32_t aval;
    const float* bcol;
    int ldb;
    uint32_t a_s;
    uint32_t b_s;
};

__device__ __forceinline__ void pipe_load(const PipeCtx& P, int ic, int st) {
    uint32_t as = P.a_s + st * (STAGE_W * 4);
    const float* ag = P.arow + ic * 32;
#pragma unroll
    for (int q = 0; q < 4; q++) cpa16(as + q * 16, ag + q * 4, P.aval);
    uint32_t bs = P.b_s + st * (STAGE_W * 4);
    const float* bg = P.bcol + (size_t)ic * 32 * P.ldb;
#pragma unroll
    for (int kq = 0; kq < 4; kq++)
        cpa16(bs + kq * (8 * LDB * 4), bg + (size_t)kq * 8 * P.ldb, 16);
    cpa_commit();
}

#define PIPE_SETUP(LDB_V, BW_PTR)                                                \
    extern __shared__ uint32_t smw[];                                            \
    const int tid  = threadIdx.x;                                                \
    const int lane = tid & 31, wid = tid >> 5;                                   \
    const int wm0 = (wid >> 2) * 64, wn0 = (wid & 3) * 32;                       \
    int* s_pair = (int*)smw;                                                     \
    if (tid < 128) {                                                             \
        int gm = m0 + tid;                                                       \
        s_pair[tid] = (gm < cnt) ? g_list[e * MAXPER + gm] : -1;                 \
    }                                                                            \
    __syncthreads();                                                             \
    PipeCtx P;                                                                   \
    {                                                                            \
        uint32_t sb = smem_u32(smw);                                             \
        P.ldb  = (LDB_V);                                                        \
        P.aval = 0; P.arow = (const float*)0;                                    \
        P.bcol = (BW_PTR) + n0 + (tid & 31) * 4 + (size_t)(tid >> 5) * (LDB_V);  \
        P.a_s  = sb + SP_W * 4 + (tid >> 1) * (LDA * 4) + (tid & 1) * 64;        \
        P.b_s  = sb + SP_W * 4 + A_ST_W * 4 + (tid >> 5) * (LDB * 4) +           \
                 (tid & 31) * 16;                                                \
    }

// single __syncthreads per chunk; stage(c) = c%3; load(i+2) at iter i
// overwrites stage (i-1)%3 which the entry sync proved fully consumed.
#define PIPE_MAINLOOP(NC)                                                        \
    float acc[4][4][4];                                                          \
    _Pragma("unroll") for (int a_ = 0; a_ < 4; a_++)                             \
    _Pragma("unroll") for (int b_ = 0; b_ < 4; b_++)                             \
    _Pragma("unroll") for (int c_ = 0; c_ < 4; c_++) acc[a_][b_][c_] = 0.f;      \
    pipe_load(P, 0, 0); pipe_load(P, 1, 1);                                      \
    for (int i = 0; i < (NC); i++) {                                             \
        int st = i % 3;                                                          \
        cpa_wait1();                                                             \
        __syncthreads();                                                         \
        if (i + 2 < (NC)) pipe_load(P, i + 2, (i + 2) % 3); else cpa_commit();   \
        const uint32_t* sA = smw + SP_W + st * STAGE_W;                          \
        const uint32_t* sB = sA + A_ST_W;                                        \
        _Pragma("unroll")                                                        \
        for (int ks = 0; ks < 32; ks += 8) {                                     \
            uint32_t bf0[4], bf1[4];                                             \
            _Pragma("unroll")                                                    \
            for (int ni = 0; ni < 4; ni++) {                                     \
                int cB = wn0 + ni * 8 + (lane >> 2);                             \
                bf0[ni] = bits2tf32(sB[(ks +     (lane & 3)) * LDB + cB]);       \
                bf1[ni] = bits2tf32(sB[(ks + 4 + (lane & 3)) * LDB + cB]);       \
            }                                                                    \
            _Pragma("unroll")                                                    \
            for (int mi = 0; mi < 4; mi++) {                                     \
                int rA = wm0 + mi * 16 + (lane >> 2);                            \
                uint2 av0 = *(const uint2*)&sA[rA * LDA + ks + 2 * (lane & 3)];  \
                uint2 av1 = *(const uint2*)&sA[(rA + 8) * LDA + ks + 2 * (lane & 3)]; \
                _Pragma("unroll")                                                \
                for (int ni = 0; ni < 4; ni++)                                   \
                    mma_tf32(acc[mi][ni], av0.x, av1.x, av0.y, av1.y,            \
                             bf0[ni], bf1[ni]);                                  \
            }                                                                    \
        }                                                                        \
    }

// ---------------- GEMM1: g_h = perm(tf32(gelu(x_g @ W1_e + b1_e))) -------------
__global__ __launch_bounds__(256, 2)
void gemm1_mma(const float* __restrict__ w1, const float* __restrict__ b1) {
    const int e   = blockIdx.z;
    const int cnt = g_cnt[e];
    const int m0  = blockIdx.y * 128;
    if (m0 >= cnt) return;
    const int n0  = blockIdx.x * 128;

    PIPE_SETUP(D_HID, (w1 + (size_t)e * D_MODEL * D_HID));
    {
        int pr = s_pair[tid >> 1];
        P.aval = (pr >= 0) ? 16u : 0u;
        P.arow = g_x + (size_t)((pr >= 0) ? (pr >> 1) : 0) * D_MODEL +
                 (tid & 1) * 16;
    }
    PIPE_MAINLOOP(D_MODEL / 32)

    // epilogue: bias + erf-GELU, tf32-rounded, permuted scatter -> g_h
#pragma unroll
    for (int mi = 0; mi < 4; mi++) {
        int r0 = wm0 + mi * 16 + (lane >> 2);
#pragma unroll
        for (int half = 0; half < 2; half++) {
            int r = r0 + half * 8;
            int pr = s_pair[r];
            if (pr < 0) continue;
            float* hrow = g_h + (size_t)pr * D_HID + n0;
#pragma unroll
            for (int ni = 0; ni < 4; ni++) {
                int c = wn0 + ni * 8 + 2 * (lane & 3);
                float2 bb = *(const float2*)(b1 + e * D_HID + n0 + c);
                float ox = gelu_f(acc[mi][ni][half * 2 + 0] + bb.x);
                float oy = gelu_f(acc[mi][ni][half * 2 + 1] + bb.y);
                hrow[permj(c)]     = __uint_as_float(f2tf32(ox));
                hrow[permj(c + 1)] = __uint_as_float(f2tf32(oy));
            }
        }
    }
}

// ---------------- GEMM2: out += wgt * (g_h @ W2_e + b2_e) ----------------------
__global__ __launch_bounds__(256, 2)
void gemm2_mma(const float* __restrict__ w2, const float* __restrict__ b2,
               float* __restrict__ out) {
    const int e   = blockIdx.z;
    const int cnt = g_cnt[e];
    const int m0  = blockIdx.y * 128;
    if (m0 >= cnt) return;
    const int n0  = blockIdx.x * 128;

    PIPE_SETUP(D_MODEL, (w2 + (size_t)e * D_HID * D_MODEL));
    {
        int pr = s_pair[tid >> 1];
        P.aval = (pr >= 0) ? 16u : 0u;
        P.arow = g_h + (size_t)((pr >= 0) ? pr : 0) * D_HID + (tid & 1) * 16;
    }
    PIPE_MAINLOOP(D_HID / 32)

    // epilogue: (acc + b2) * wgt -> atomicAdd out (out is NOT permuted)
#pragma unroll
    for (int mi = 0; mi < 4; mi++) {
        int r0 = wm0 + mi * 16 + (lane >> 2);
#pragma unroll
        for (int half = 0; half < 2; half++) {
            int r = r0 + half * 8;
            int pr = s_pair[r];
            if (pr < 0) continue;
            int tok = pr >> 1;
            float w = g_wgt[pr];
            float* orow = out + (size_t)tok * D_MODEL + n0;
#pragma unroll
            for (int ni = 0; ni < 4; ni++) {
                int c = wn0 + ni * 8 + 2 * (lane & 3);
                float2 bb = *(const float2*)(b2 + e * D_MODEL + n0 + c);
                atomicAdd(&orow[c],     (acc[mi][ni][half * 2 + 0] + bb.x) * w);
                atomicAdd(&orow[c + 1], (acc[mi][ni][half * 2 + 1] + bb.y) * w);
            }
        }
    }
}

// ---------------- launch ------------------------------------------------------
extern "C" void kernel_launch(void* const* d_in, const int* in_sizes, int n_in,
                              void* d_out, int out_size) {
    const float* x  = (const float*)d_in[0];
    const float* gw = (const float*)d_in[1];
    const float* w1 = (const float*)d_in[2];
    const float* b1 = (const float*)d_in[3];
    const float* w2 = (const float*)d_in[4];
    const float* b2 = (const float*)d_in[5];
    float* out = (float*)d_out;

    cudaFuncSetAttribute(gemm1_mma, cudaFuncAttributeMaxDynamicSharedMemorySize, SMEM_BYTES);
    cudaFuncSetAttribute(gemm2_mma, cudaFuncAttributeMaxDynamicSharedMemorySize, SMEM_BYTES);

    init_kernel<<<(NTOK * D_MODEL / 4) / 256, 256>>>(out, x);
    router_kernel<<<NTOK / 8, 256>>>(x, gw);
    gemm1_mma<<<dim3(D_HID / 128, MAXPER / 128, NE), 256, SMEM_BYTES>>>(w1, b1);
    gemm2_mma<<<dim3(D_MODEL / 128, MAXPER / 128, NE), 256, SMEM_BYTES>>>(w2, b2, out);
}

// round 15
// speedup vs baseline: 1.1756x; 1.1756x over previous
#include <cuda_runtime.h>
#include <math.h>
#include <stdint.h>

#define D_MODEL 768
#define D_HID   3072
#define NE      8
#define NTOK    2048
#define NPAIR   (NTOK * 2)
#define MAXPER  2048

// g_x / g_h hold tf32-rounded values, fragment-permuted within each 8-word
// k-group (stored [k0,k4,k1,k5,k2,k6,k3,k7]) so an MMA thread's (ks+c, ks+4+c)
// operand pair is one contiguous LDS.64.
__device__ float g_h[(size_t)NPAIR * D_HID];
__device__ float g_x[(size_t)NTOK * D_MODEL];
__device__ float g_wgt[NPAIR];
__device__ int   g_list[NE * MAXPER];
__device__ int   g_cnt[NE];

// ---------------- helpers ------------------------------------------------------
__device__ __forceinline__ uint32_t smem_u32(const void* p) {
    uint32_t a;
    asm("{ .reg .u64 t; cvta.to.shared.u64 t, %1; cvt.u32.u64 %0, t; }" : "=r"(a) : "l"(p));
    return a;
}
__device__ __forceinline__ uint32_t f2tf32(float v) {
    uint32_t r;
    asm("cvt.rna.tf32.f32 %0, %1;" : "=r"(r) : "f"(v));
    return r;
}
__device__ __forceinline__ uint32_t bits2tf32(uint32_t b) {
    return f2tf32(__uint_as_float(b));
}
__device__ __forceinline__ void mma_tf32(float* c, uint32_t a0, uint32_t a1,
                                         uint32_t a2, uint32_t a3,
                                         uint32_t b0, uint32_t b1) {
    asm volatile(
        "mma.sync.aligned.m16n8k8.row.col.f32.tf32.tf32.f32 "
        "{%0,%1,%2,%3}, {%4,%5,%6,%7}, {%8,%9}, {%0,%1,%2,%3};"
        : "+f"(c[0]), "+f"(c[1]), "+f"(c[2]), "+f"(c[3])
        : "r"(a0), "r"(a1), "r"(a2), "r"(a3), "r"(b0), "r"(b1));
}
__device__ __forceinline__ void cpa16(uint32_t saddr, const void* g, uint32_t nbytes) {
    asm volatile("cp.async.cg.shared.global [%0], [%1], 16, %2;"
                 :: "r"(saddr), "l"(g), "r"(nbytes) : "memory");
}
__device__ __forceinline__ void cpa_commit() {
    asm volatile("cp.async.commit_group;" ::: "memory");
}
__device__ __forceinline__ void cpa_wait1() {
    asm volatile("cp.async.wait_group 1;" ::: "memory");
}
__device__ __forceinline__ float gelu_f(float v) {
    return 0.5f * v * (1.0f + erff(v * 0.70710678118654752f));
}
__device__ __forceinline__ int permj(int c) {
    return (c & ~7) + 2 * (c & 3) + ((c >> 2) & 1);
}

// smem (words): [0..64) s_pair, then 2 stages of (A 64x40 | B 32x136)
#define LDA 40
#define LDB 136
#define A_ST_W (64 * LDA)               // 2560
#define B_ST_W (32 * LDB)               // 4352
#define STAGE_W (A_ST_W + B_ST_W)       // 6912 words = 27648 B
#define SP_W 64
#define SMEM_BYTES ((SP_W + 2 * STAGE_W) * 4)   // 55552 -> 3 CTAs/SM

// ---------------- init: zero out + counters + permuted tf32 x -------------------
__global__ __launch_bounds__(256)
void init_kernel(float* __restrict__ out, const float* __restrict__ x) {
    int i = blockIdx.x * blockDim.x + threadIdx.x;
    if (i < NE) g_cnt[i] = 0;
    ((float4*)out)[i] = make_float4(0.f, 0.f, 0.f, 0.f);
    int j0 = 4 * i;
    float4 r;
    float* rp = (float*)&r;
#pragma unroll
    for (int q = 0; q < 4; q++) {
        int j = j0 + q;
        int k = (j & ~7) + ((j >> 1) & 3) + 4 * (j & 1);
        rp[q] = __uint_as_float(f2tf32(x[k]));
    }
    ((float4*)g_x)[i] = r;
}

// ---------------- router: one warp per token ----------------------------------
__global__ __launch_bounds__(256)
void router_kernel(const float* __restrict__ x, const float* __restrict__ gw) {
    int gwarp = (blockIdx.x * blockDim.x + threadIdx.x) >> 5;
    int lane  = threadIdx.x & 31;
    if (gwarp >= NTOK) return;
    const float* xr = x + (size_t)gwarp * D_MODEL;

    float acc[NE];
#pragma unroll
    for (int e = 0; e < NE; e++) acc[e] = 0.f;
    for (int d = lane; d < D_MODEL; d += 32) {
        float xv = xr[d];
#pragma unroll
        for (int e = 0; e < NE; e++) acc[e] += xv * gw[d * NE + e];
    }
#pragma unroll
    for (int e = 0; e < NE; e++) {
#pragma unroll
        for (int off = 16; off > 0; off >>= 1)
            acc[e] += __shfl_xor_sync(0xffffffffu, acc[e], off);
    }
    if (lane == 0) {
        float mx = acc[0];
#pragma unroll
        for (int e = 1; e < NE; e++) mx = fmaxf(mx, acc[e]);
        float p[NE];
#pragma unroll
        for (int e = 0; e < NE; e++) p[e] = __expf(acc[e] - mx);
        int i0 = 0;
#pragma unroll
        for (int e = 1; e < NE; e++) if (p[e] > p[i0]) i0 = e;
        int i1 = (i0 == 0) ? 1 : 0;
#pragma unroll
        for (int e = 0; e < NE; e++) if (e != i0 && p[e] > p[i1]) i1 = e;
        float s2 = p[i0] + p[i1];
        int pr0 = gwarp * 2, pr1 = gwarp * 2 + 1;
        g_wgt[pr0] = p[i0] / s2;
        g_wgt[pr1] = p[i1] / s2;
        int pos0 = atomicAdd(&g_cnt[i0], 1);
        g_list[i0 * MAXPER + pos0] = pr0;
        int pos1 = atomicAdd(&g_cnt[i1], 1);
        g_list[i1 * MAXPER + pos1] = pr1;
    }
}

// ======================= pipelined tf32 MMA GEMM bodies ========================
// CTA tile 64(M)x128(N), 256 thr / 8 warps (2m x 4n), warp tile 32x32, KC=32,
// 2-stage cp.async ring, 3 CTAs/SM.
struct PipeCtx {
    const float* arow;
    uint32_t aval;
    const float* bcol;
    int ldb;
    uint32_t a_s;
    uint32_t b_s;
};

__device__ __forceinline__ void pipe_load(const PipeCtx& P, int ic, int st) {
    uint32_t as = P.a_s + st * (STAGE_W * 4);
    const float* ag = P.arow + ic * 32;
#pragma unroll
    for (int q = 0; q < 2; q++) cpa16(as + q * 16, ag + q * 4, P.aval);
    uint32_t bs = P.b_s + st * (STAGE_W * 4);
    const float* bg = P.bcol + (size_t)ic * 32 * P.ldb;
#pragma unroll
    for (int kq = 0; kq < 4; kq++)
        cpa16(bs + kq * (8 * LDB * 4), bg + (size_t)kq * 8 * P.ldb, 16);
    cpa_commit();
}

#define PIPE_SETUP(LDB_V, BW_PTR)                                                \
    extern __shared__ uint32_t smw[];                                            \
    const int tid  = threadIdx.x;                                                \
    const int lane = tid & 31, wid = tid >> 5;                                   \
    const int wm0 = (wid >> 2) * 32, wn0 = (wid & 3) * 32;                       \
    int* s_pair = (int*)smw;                                                     \
    if (tid < 64) {                                                              \
        int gm = m0 + tid;                                                       \
        s_pair[tid] = (gm < cnt) ? g_list[e * MAXPER + gm] : -1;                 \
    }                                                                            \
    __syncthreads();                                                             \
    PipeCtx P;                                                                   \
    {                                                                            \
        uint32_t sb = smem_u32(smw);                                             \
        P.ldb  = (LDB_V);                                                        \
        P.aval = 0; P.arow = (const float*)0;                                    \
        P.bcol = (BW_PTR) + n0 + (tid & 31) * 4 + (size_t)(tid >> 5) * (LDB_V);  \
        P.a_s  = sb + SP_W * 4 + (tid >> 2) * (LDA * 4) + (tid & 3) * 32;        \
        P.b_s  = sb + SP_W * 4 + A_ST_W * 4 + (tid >> 5) * (LDB * 4) +           \
                 (tid & 31) * 16;                                                \
    }

// 2-stage, two syncs per chunk (R9-proven shape): wait1 -> sync -> compute ->
// sync -> load(i+2) into the just-consumed stage.
#define PIPE_MAINLOOP(NC)                                                        \
    float acc[2][4][4];                                                          \
    _Pragma("unroll") for (int a_ = 0; a_ < 2; a_++)                             \
    _Pragma("unroll") for (int b_ = 0; b_ < 4; b_++)                             \
    _Pragma("unroll") for (int c_ = 0; c_ < 4; c_++) acc[a_][b_][c_] = 0.f;      \
    pipe_load(P, 0, 0); pipe_load(P, 1, 1);                                      \
    for (int i = 0; i < (NC); i++) {                                             \
        int st = i & 1;                                                          \
        cpa_wait1();                                                             \
        __syncthreads();                                                         \
        const uint32_t* sA = smw + SP_W + st * STAGE_W;                          \
        const uint32_t* sB = sA + A_ST_W;                                        \
        _Pragma("unroll")                                                        \
        for (int ks = 0; ks < 32; ks += 8) {                                     \
            uint32_t bf0[4], bf1[4];                                             \
            _Pragma("unroll")                                                    \
            for (int ni = 0; ni < 4; ni++) {                                     \
                int cB = wn0 + ni * 8 + (lane >> 2);                             \
                bf0[ni] = bits2tf32(sB[(ks +     (lane & 3)) * LDB + cB]);       \
                bf1[ni] = bits2tf32(sB[(ks + 4 + (lane & 3)) * LDB + cB]);       \
            }                                                                    \
            _Pragma("unroll")                                                    \
            for (int mi = 0; mi < 2; mi++) {                                     \
                int rA = wm0 + mi * 16 + (lane >> 2);                            \
                uint2 av0 = *(const uint2*)&sA[rA * LDA + ks + 2 * (lane & 3)];  \
                uint2 av1 = *(const uint2*)&sA[(rA + 8) * LDA + ks + 2 * (lane & 3)]; \
                _Pragma("unroll")                                                \
                for (int ni = 0; ni < 4; ni++)                                   \
                    mma_tf32(acc[mi][ni], av0.x, av1.x, av0.y, av1.y,            \
                             bf0[ni], bf1[ni]);                                  \
            }                                                                    \
        }                                                                        \
        __syncthreads();                                                         \
        if (i + 2 < (NC)) pipe_load(P, i + 2, st); else cpa_commit();            \
    }

// ---------------- GEMM1: g_h = perm(tf32(gelu(x_g @ W1_e + b1_e))) -------------
__global__ __launch_bounds__(256, 3)
void gemm1_mma(const float* __restrict__ w1, const float* __restrict__ b1) {
    const int e   = blockIdx.z;
    const int cnt = g_cnt[e];
    const int m0  = blockIdx.y * 64;
    if (m0 >= cnt) return;
    const int n0  = blockIdx.x * 128;

    PIPE_SETUP(D_HID, (w1 + (size_t)e * D_MODEL * D_HID));
    {
        int pr = s_pair[tid >> 2];
        P.aval = (pr >= 0) ? 16u : 0u;
        P.arow = g_x + (size_t)((pr >= 0) ? (pr >> 1) : 0) * D_MODEL +
                 (tid & 3) * 8;
    }
    PIPE_MAINLOOP(D_MODEL / 32)

#pragma unroll
    for (int mi = 0; mi < 2; mi++) {
        int r0 = wm0 + mi * 16 + (lane >> 2);
#pragma unroll
        for (int half = 0; half < 2; half++) {
            int r = r0 + half * 8;
            int pr = s_pair[r];
            if (pr < 0) continue;
            float* hrow = g_h + (size_t)pr * D_HID + n0;
#pragma unroll
            for (int ni = 0; ni < 4; ni++) {
                int c = wn0 + ni * 8 + 2 * (lane & 3);
                float2 bb = *(const float2*)(b1 + e * D_HID + n0 + c);
                float ox = gelu_f(acc[mi][ni][half * 2 + 0] + bb.x);
                float oy = gelu_f(acc[mi][ni][half * 2 + 1] + bb.y);
                hrow[permj(c)]     = __uint_as_float(f2tf32(ox));
                hrow[permj(c + 1)] = __uint_as_float(f2tf32(oy));
            }
        }
    }
}

// ---------------- GEMM2: out += wgt * (g_h @ W2_e + b2_e) ----------------------
__global__ __launch_bounds__(256, 3)
void gemm2_mma(const float* __restrict__ w2, const float* __restrict__ b2,
               float* __restrict__ out) {
    const int e   = blockIdx.z;
    const int cnt = g_cnt[e];
    const int m0  = blockIdx.y * 64;
    if (m0 >= cnt) return;
    const int n0  = blockIdx.x * 128;

    PIPE_SETUP(D_MODEL, (w2 + (size_t)e * D_HID * D_MODEL));
    {
        int pr = s_pair[tid >> 2];
        P.aval = (pr >= 0) ? 16u : 0u;
        P.arow = g_h + (size_t)((pr >= 0) ? pr : 0) * D_HID + (tid & 3) * 8;
    }
    PIPE_MAINLOOP(D_HID / 32)

#pragma unroll
    for (int mi = 0; mi < 2; mi++) {
        int r0 = wm0 + mi * 16 + (lane >> 2);
#pragma unroll
        for (int half = 0; half < 2; half++) {
            int r = r0 + half * 8;
            int pr = s_pair[r];
            if (pr < 0) continue;
            int tok = pr >> 1;
            float w = g_wgt[pr];
            float* orow = out + (size_t)tok * D_MODEL + n0;
#pragma unroll
            for (int ni = 0; ni < 4; ni++) {
                int c = wn0 + ni * 8 + 2 * (lane & 3);
                float2 bb = *(const float2*)(b2 + e * D_MODEL + n0 + c);
                atomicAdd(&orow[c],     (acc[mi][ni][half * 2 + 0] + bb.x) * w);
                atomicAdd(&orow[c + 1], (acc[mi][ni][half * 2 + 1] + bb.y) * w);
            }
        }
    }
}

// ---------------- launch ------------------------------------------------------
extern "C" void kernel_launch(void* const* d_in, const int* in_sizes, int n_in,
                              void* d_out, int out_size) {
    const float* x  = (const float*)d_in[0];
    const float* gw = (const float*)d_in[1];
    const float* w1 = (const float*)d_in[2];
    const float* b1 = (const float*)d_in[3];
    const float* w2 = (const float*)d_in[4];
    const float* b2 = (const float*)d_in[5];
    float* out = (float*)d_out;

    cudaFuncSetAttribute(gemm1_mma, cudaFuncAttributeMaxDynamicSharedMemorySize, SMEM_BYTES);
    cudaFuncSetAttribute(gemm2_mma, cudaFuncAttributeMaxDynamicSharedMemorySize, SMEM_BYTES);

    init_kernel<<<(NTOK * D_MODEL / 4) / 256, 256>>>(out, x);
    router_kernel<<<NTOK / 8, 256>>>(x, gw);
    gemm1_mma<<<dim3(D_HID / 128, MAXPER / 64, NE), 256, SMEM_BYTES>>>(w1, b1);
    gemm2_mma<<<dim3(D_MODEL / 128, MAXPER / 64, NE), 256, SMEM_BYTES>>>(w2, b2, out);
}